// round 11
// baseline (speedup 1.0000x reference)
#include <cuda_runtime.h>
#include <cuda_fp16.h>
#include <cstdint>

#define BB 256      // batch
#define SS 256      // encoder seq len
#define DD 64       // input dim
#define HH 1024     // hidden
#define G4 4096     // 4*H
#define TOUT 32     // decode steps
#define APAD 72     // smem row stride (halfs) = 144B

// ---------------- static device scratch (fp16 operands, fp32 state) --------
__device__ __half g_W0enc[(size_t)G4 * 1088];   // [Whh0 | Wih0]
__device__ __half g_W1enc[(size_t)G4 * 2048];   // [Whh1 | Wih1]
__device__ __half g_W0dec[(size_t)G4 * 1024];   // dec Whh0
__device__ __half g_W1dec[(size_t)G4 * 2048];   // [dec Whh1 | dec Wih1]
__device__ __half g_X[(size_t)BB * SS * DD];    // fp16 X
__device__ __half g_h0[2][BB * HH];
__device__ __half g_h1[2][BB * HH];
__device__ float  g_c0[BB * HH];
__device__ float  g_c1[BB * HH];
__device__ float  g_pred[BB];

__device__ __forceinline__ float sigmoidf_(float x) { return 1.0f / (1.0f + expf(-x)); }

__device__ __forceinline__ void cpa16(void* s, const void* g) {
    unsigned sa = (unsigned)__cvta_generic_to_shared(s);
    asm volatile("cp.async.ca.shared.global [%0], [%1], 16;\n" ::"r"(sa), "l"(g));
}
__device__ __forceinline__ void cpa_commit() { asm volatile("cp.async.commit_group;\n"); }
__device__ __forceinline__ void cpa_wait0() { asm volatile("cp.async.wait_group 0;\n"); }

__device__ __forceinline__ uint32_t smem_u32(const void* p) {
    uint32_t a;
    asm("{ .reg .u64 t; cvta.to.shared.u64 t, %1; cvt.u32.u64 %0, t; }" : "=r"(a) : "l"(p));
    return a;
}
__device__ __forceinline__ void ldsm_x4(uint32_t& r0, uint32_t& r1, uint32_t& r2, uint32_t& r3,
                                        uint32_t addr) {
    asm volatile("ldmatrix.sync.aligned.m8n8.x4.shared.b16 {%0,%1,%2,%3}, [%4];"
                 : "=r"(r0), "=r"(r1), "=r"(r2), "=r"(r3) : "r"(addr));
}
__device__ __forceinline__ void mma16816(float* c, uint32_t a0, uint32_t a1, uint32_t a2,
                                         uint32_t a3, uint32_t b0, uint32_t b1) {
    asm volatile(
        "mma.sync.aligned.m16n8k16.row.col.f32.f16.f16.f32 "
        "{%0,%1,%2,%3},{%4,%5,%6,%7},{%8,%9},{%0,%1,%2,%3};"
        : "+f"(c[0]), "+f"(c[1]), "+f"(c[2]), "+f"(c[3])
        : "r"(a0), "r"(a1), "r"(a2), "r"(a3), "r"(b0), "r"(b1));
}

// ---------------- setup: fp16 conversion, zero states ----------
__global__ void setup_kernel(const float* __restrict__ X,
                             const float* __restrict__ eWih0, const float* __restrict__ eWhh0,
                             const float* __restrict__ eWih1, const float* __restrict__ eWhh1,
                             const float* __restrict__ dWhh0,
                             const float* __restrict__ dWih1, const float* __restrict__ dWhh1)
{
    const size_t s0 = (size_t)G4 * 1088;
    const size_t s1 = (size_t)G4 * 2048;
    const size_t s2 = (size_t)G4 * 2048;
    const size_t s3 = (size_t)G4 * 1024;
    const size_t sx = (size_t)BB * SS * DD;
    const size_t s4 = (size_t)4 * BB * HH;
    const size_t s5 = BB;
    const size_t total = s0 + s1 + s2 + s3 + sx + s4 + s5;

    for (size_t i = (size_t)blockIdx.x * blockDim.x + threadIdx.x; i < total;
         i += (size_t)gridDim.x * blockDim.x) {
        size_t x = i;
        if (x < s0) {
            size_t r = x / 1088, k = x % 1088;
            float v = (k < 1024) ? eWhh0[r * 1024 + k] : eWih0[r * 64 + (k - 1024)];
            g_W0enc[x] = __float2half_rn(v);
            continue;
        }
        x -= s0;
        if (x < s1) {
            size_t r = x / 2048, k = x % 2048;
            float v = (k < 1024) ? eWhh1[r * 1024 + k] : eWih1[r * 1024 + (k - 1024)];
            g_W1enc[x] = __float2half_rn(v);
            continue;
        }
        x -= s1;
        if (x < s2) {
            size_t r = x / 2048, k = x % 2048;
            float v = (k < 1024) ? dWhh1[r * 1024 + k] : dWih1[r * 1024 + (k - 1024)];
            g_W1dec[x] = __float2half_rn(v);
            continue;
        }
        x -= s2;
        if (x < s3) { g_W0dec[x] = __float2half_rn(dWhh0[x]); continue; }
        x -= s3;
        if (x < sx) { g_X[x] = __float2half_rn(X[x]); continue; }
        x -= sx;
        if (x < s4) {
            size_t seg = x / ((size_t)BB * HH);
            size_t off = x % ((size_t)BB * HH);
            if (seg == 0) g_h0[0][off] = __float2half_rn(0.0f);
            else if (seg == 1) g_h1[0][off] = __float2half_rn(0.0f);
            else if (seg == 2) g_c0[off] = 0.0f;
            else g_c1[off] = 0.0f;
            continue;
        }
        x -= s4;
        g_pred[x] = 0.0f;
    }
}

// ---------------- fused LSTM cell GEMM: explicit mma.m16n8k16 ----------------
// CTA: 128 threads = 4 warps (2m x 2n), warp tile 64x32. CTA tile M=128 x N=64.
// K-chunk 64 halfs, 2-stage cp.async ring, 4 CTAs/SM.
#define NSTG 2
#define MT 128
#define KC 64
#define ASZ (MT * APAD)              // halfs
#define BSZ (64 * APAD)
#define STG_H (ASZ + BSZ)            // halfs per stage
#define SMEM_BYTES (NSTG * STG_H * 2)   // 55296 B
#define CPAD 72                      // C row stride (floats)

struct Role {
    const __half* W;       // weight, row-major [4096, K]
    const __half* Ah;      // h part of A (row stride HH)
    const __half* aux;     // second A part base
    size_t aux_stride;     // row stride of aux
    __half* hout;
    float* c_io;
    const float* bias;     // [4096]
    const float* sw;       // scalar-input weights [4096] or null
    int K;
};

__device__ __forceinline__ void cell_body(const Role& R, int mt, int jt, __half* smem, int tid)
{
    const int j0 = jt * 16;
    const int m0 = mt * MT;
    const int warp = tid >> 5, lane = tid & 31;
    const int wm = warp & 1;       // 64-row half
    const int wn = warp >> 1;      // 32-col half
    const int nch = R.K / KC;
    const uint32_t sb = smem_u32(smem);

    // per-lane ldmatrix byte offsets within a stage
    const uint32_t aOff =
        ((uint32_t)(wm * 64 + (lane & 15)) * APAD + ((lane >> 4) & 1) * 8) * 2;
    const uint32_t bOff = (uint32_t)ASZ * 2 +
        ((uint32_t)(wn * 32 + ((lane & 16) >> 1) + (lane & 7)) * APAD + ((lane & 8) ? 8 : 0)) * 2;

    auto load_chunk = [&](int ck) {
        __half* a = smem + (ck & (NSTG - 1)) * STG_H;
        __half* b = a + ASZ;
        const int kk = ck * KC;
#pragma unroll
        for (int it = 0; it < 8; it++) {
            int u = tid + it * 128;          // 0..1023 : 128 rows x 8 segs
            int r = u >> 3, c8 = (u & 7) << 3;
            int kg = kk + c8;
            const __half* src = (kg < 1024)
                ? R.Ah + (size_t)(m0 + r) * HH + kg
                : R.aux + (size_t)(m0 + r) * R.aux_stride + (kg - 1024);
            cpa16(a + r * APAD + c8, src);
        }
#pragma unroll
        for (int it = 0; it < 4; it++) {
            int u = tid + it * 128;          // 0..511 : 64 rows x 8 segs
            int n = u >> 3, c8 = (u & 7) << 3;
            int g = n >> 4, jj = n & 15;
            const __half* src = R.W + (size_t)(g * 1024 + j0 + jj) * R.K + kk + c8;
            cpa16(b + n * APAD + c8, src);
        }
        cpa_commit();
    };

    float acc[4][4][4];
#pragma unroll
    for (int mi = 0; mi < 4; mi++)
#pragma unroll
        for (int ni = 0; ni < 4; ni++)
#pragma unroll
            for (int e = 0; e < 4; e++) acc[mi][ni][e] = 0.0f;

    load_chunk(0);

    for (int ck = 0; ck < nch; ck++) {
        cpa_wait0();
        __syncthreads();            // chunk ck visible; all warps done with ck-1
        if (ck + 1 < nch) load_chunk(ck + 1);

        const uint32_t stg = sb + (uint32_t)(ck & (NSTG - 1)) * (STG_H * 2);
#pragma unroll
        for (int k16 = 0; k16 < KC / 16; k16++) {
            const uint32_t kb = (uint32_t)k16 * 32;   // 16 halfs
            uint32_t b0[4], b1[4];
            ldsm_x4(b0[0], b0[1], b0[2], b0[3], stg + bOff + kb);                  // n-tiles 0,1
            ldsm_x4(b1[0], b1[1], b1[2], b1[3], stg + bOff + kb + 16 * APAD * 2);  // n-tiles 2,3
#pragma unroll
            for (int mi = 0; mi < 4; mi++) {
                uint32_t a0, a1, a2, a3;
                ldsm_x4(a0, a1, a2, a3, stg + aOff + kb + (uint32_t)mi * 16 * APAD * 2);
                mma16816(acc[mi][0], a0, a1, a2, a3, b0[0], b0[1]);
                mma16816(acc[mi][1], a0, a1, a2, a3, b0[2], b0[3]);
                mma16816(acc[mi][2], a0, a1, a2, a3, b1[0], b1[1]);
                mma16816(acc[mi][3], a0, a1, a2, a3, b1[2], b1[3]);
            }
        }
    }
    __syncthreads();   // compute done before C overwrites stage smem

    // --- epilogue: dump C [128][CPAD] fp32, cell update ---
    float* Cs = (float*)smem;
    {
        const int rr = lane >> 2, cc = 2 * (lane & 3);
#pragma unroll
        for (int mi = 0; mi < 4; mi++)
#pragma unroll
            for (int ni = 0; ni < 4; ni++) {
                int r0 = wm * 64 + mi * 16 + rr;
                int c0 = wn * 32 + ni * 8 + cc;
                Cs[r0 * CPAD + c0]           = acc[mi][ni][0];
                Cs[r0 * CPAD + c0 + 1]       = acc[mi][ni][1];
                Cs[(r0 + 8) * CPAD + c0]     = acc[mi][ni][2];
                Cs[(r0 + 8) * CPAD + c0 + 1] = acc[mi][ni][3];
            }
    }
    __syncthreads();

#pragma unroll
    for (int e = 0; e < 16; e++) {
        int idx = tid + e * 128;     // 0..2047 = 128 rows x 16 j
        int r = idx >> 4;
        int jj = idx & 15;
        int b = m0 + r;
        int j = j0 + jj;

        float gi = Cs[r * CPAD + 0 * 16 + jj] + R.bias[j];
        float gf = Cs[r * CPAD + 1 * 16 + jj] + R.bias[1024 + j];
        float gg = Cs[r * CPAD + 2 * 16 + jj] + R.bias[2048 + j];
        float go = Cs[r * CPAD + 3 * 16 + jj] + R.bias[3072 + j];

        if (R.sw) {
            float p = g_pred[b];
            gi += p * R.sw[j];
            gf += p * R.sw[1024 + j];
            gg += p * R.sw[2048 + j];
            go += p * R.sw[3072 + j];
        }

        size_t o = (size_t)b * HH + j;
        float c  = R.c_io[o];
        float cn = sigmoidf_(gf) * c + sigmoidf_(gi) * tanhf(gg);
        float hn = sigmoidf_(go) * tanhf(cn);
        R.c_io[o] = cn;
        R.hout[o] = __float2half_rn(hn);
    }
}

// mode: 0 = encoder fused [L1(t) | L0(t+1)], 1 = enc L0(t), 2 = enc L1(t),
//       3 = dec L0(t), 4 = dec L1(t)
__global__ void __launch_bounds__(128, 4)
cell_kernel(const float* __restrict__ bias0, const float* __restrict__ bias1,
            const float* __restrict__ sw0, int t, int par, int mode)
{
    extern __shared__ __half smem[];
    const int tid = threadIdx.x;

    int roleL1, local;
    if (mode == 0) { roleL1 = (blockIdx.x < 128); local = blockIdx.x & 127; }
    else           { roleL1 = (mode == 2 || mode == 4); local = blockIdx.x; }
    const int mt = local & 1;
    const int jt = local >> 1;

    Role R;
    if (mode <= 2) {
        if (roleL1) {  // encoder layer 1, step t
            R.W = g_W1enc; R.K = 2048;
            R.Ah = g_h1[par]; R.aux = g_h0[par ^ 1]; R.aux_stride = HH;
            R.hout = g_h1[par ^ 1]; R.c_io = g_c1;
            R.bias = bias1; R.sw = nullptr;
        } else {       // encoder layer 0, step s
            int s, parS;
            if (mode == 0) { s = t + 1; parS = par ^ 1; }
            else           { s = t;     parS = par;     }
            R.W = g_W0enc; R.K = 1088;
            R.Ah = g_h0[parS]; R.aux = g_X + (size_t)s * DD; R.aux_stride = (size_t)SS * DD;
            R.hout = g_h0[parS ^ 1]; R.c_io = g_c0;
            R.bias = bias0; R.sw = nullptr;
        }
    } else if (mode == 3) {   // decoder layer 0
        R.W = g_W0dec; R.K = 1024;
        R.Ah = g_h0[par]; R.aux = g_h0[par]; R.aux_stride = HH;  // aux unused
        R.hout = g_h0[par ^ 1]; R.c_io = g_c0;
        R.bias = bias0; R.sw = sw0;
    } else {                  // decoder layer 1
        R.W = g_W1dec; R.K = 2048;
        R.Ah = g_h1[par]; R.aux = g_h0[par ^ 1]; R.aux_stride = HH;
        R.hout = g_h1[par ^ 1]; R.c_io = g_c1;
        R.bias = bias1; R.sw = nullptr;
    }

    cell_body(R, mt, jt, smem, tid);
}

// ---------------- fc: pred[b] = dot(h1[b], fcW) + fcb ----------------------
__global__ void fc_kernel(const float* __restrict__ fcW, const float* __restrict__ fcb,
                          float* __restrict__ out, int par, int t)
{
    int gw = (blockIdx.x * blockDim.x + threadIdx.x) >> 5;
    int lane = threadIdx.x & 31;
    if (gw >= BB) return;
    const __half* hr = g_h1[par] + (size_t)gw * HH;
    float s = 0.0f;
#pragma unroll 8
    for (int k = lane; k < HH; k += 32) s += __half2float(hr[k]) * fcW[k];
#pragma unroll
    for (int o = 16; o; o >>= 1) s += __shfl_xor_sync(0xFFFFFFFFu, s, o);
    if (lane == 0) {
        float p = s + fcb[0];
        out[(size_t)gw * TOUT + t] = p;
        g_pred[gw] = p;
    }
}

// ---------------- launch ----------------------------------------------------
extern "C" void kernel_launch(void* const* d_in, const int* in_sizes, int n_in,
                              void* d_out, int out_size)
{
    const float* X     = (const float*)d_in[0];
    const float* eWih0 = (const float*)d_in[1];
    const float* eWhh0 = (const float*)d_in[2];
    const float* eb0   = (const float*)d_in[3];
    const float* eWih1 = (const float*)d_in[4];
    const float* eWhh1 = (const float*)d_in[5];
    const float* eb1   = (const float*)d_in[6];
    const float* dWih0 = (const float*)d_in[7];
    const float* dWhh0 = (const float*)d_in[8];
    const float* db0   = (const float*)d_in[9];
    const float* dWih1 = (const float*)d_in[10];
    const float* dWhh1 = (const float*)d_in[11];
    const float* db1   = (const float*)d_in[12];
    const float* fcW   = (const float*)d_in[13];
    const float* fcb   = (const float*)d_in[14];
    float* out         = (float*)d_out;

    cudaFuncSetAttribute(cell_kernel, cudaFuncAttributeMaxDynamicSharedMemorySize,
                         SMEM_BYTES);

    setup_kernel<<<1024, 256>>>(X, eWih0, eWhh0, eWih1, eWhh1, dWhh0, dWih1, dWhh1);

    // encoder: software-pipelined wavefront (L1(t) runs with L0(t+1) in one launch)
    cell_kernel<<<128, 128, SMEM_BYTES>>>(eb0, nullptr, nullptr, 0, 0, 1);      // L0(0)
    for (int t = 0; t < SS - 1; t++)
        cell_kernel<<<256, 128, SMEM_BYTES>>>(eb0, eb1, nullptr, t, t & 1, 0);  // L1(t)+L0(t+1)
    cell_kernel<<<128, 128, SMEM_BYTES>>>(nullptr, eb1, nullptr, SS - 1, (SS - 1) & 1, 2);

    // decoder (final enc states in g_h0[0], g_h1[0])
    int par = 0;
    for (int t = 0; t < TOUT; t++) {
        cell_kernel<<<128, 128, SMEM_BYTES>>>(db0, nullptr, dWih0, t, par, 3);
        cell_kernel<<<128, 128, SMEM_BYTES>>>(nullptr, db1, nullptr, t, par, 4);
        fc_kernel<<<8, 1024>>>(fcW, fcb, out, par ^ 1, t);
        par ^= 1;
    }
}

// round 12
// speedup vs baseline: 1.2945x; 1.2945x over previous
#include <cuda_runtime.h>
#include <cuda_fp16.h>
#include <cstdint>

#define BB 256      // batch
#define SS 256      // encoder seq len
#define DD 64       // input dim
#define HH 1024     // hidden
#define G4 4096     // 4*H
#define TOUT 32     // decode steps
#define APAD 72     // smem row stride (halfs) = 144B

// ---------------- static device scratch (fp16 operands, fp32 state) --------
__device__ __half g_W0enc[(size_t)G4 * 1088];   // [Whh0 | Wih0]
__device__ __half g_W1enc[(size_t)G4 * 2048];   // [Whh1 | Wih1]
__device__ __half g_W0dec[(size_t)G4 * 1024];   // dec Whh0
__device__ __half g_W1dec[(size_t)G4 * 2048];   // [dec Whh1 | dec Wih1]
__device__ __half g_X[(size_t)BB * SS * DD];    // fp16 X
__device__ __half g_h0[2][BB * HH];
__device__ __half g_h1[2][BB * HH];
__device__ float  g_c0[BB * HH];
__device__ float  g_c1[BB * HH];
__device__ float  g_pred[BB];

__device__ __forceinline__ float sigmoidf_(float x) { return 1.0f / (1.0f + expf(-x)); }

__device__ __forceinline__ void cpa16(void* s, const void* g) {
    unsigned sa = (unsigned)__cvta_generic_to_shared(s);
    asm volatile("cp.async.ca.shared.global [%0], [%1], 16;\n" ::"r"(sa), "l"(g));
}
__device__ __forceinline__ void cpa_commit() { asm volatile("cp.async.commit_group;\n"); }
__device__ __forceinline__ void cpa_wait2() { asm volatile("cp.async.wait_group 2;\n"); }
__device__ __forceinline__ void cpa_wait1() { asm volatile("cp.async.wait_group 1;\n"); }
__device__ __forceinline__ void cpa_wait0() { asm volatile("cp.async.wait_group 0;\n"); }

__device__ __forceinline__ uint32_t smem_u32(const void* p) {
    uint32_t a;
    asm("{ .reg .u64 t; cvta.to.shared.u64 t, %1; cvt.u32.u64 %0, t; }" : "=r"(a) : "l"(p));
    return a;
}
__device__ __forceinline__ void ldsm_x4(uint32_t& r0, uint32_t& r1, uint32_t& r2, uint32_t& r3,
                                        uint32_t addr) {
    asm volatile("ldmatrix.sync.aligned.m8n8.x4.shared.b16 {%0,%1,%2,%3}, [%4];"
                 : "=r"(r0), "=r"(r1), "=r"(r2), "=r"(r3) : "r"(addr));
}
__device__ __forceinline__ void mma16816(float* c, uint32_t a0, uint32_t a1, uint32_t a2,
                                         uint32_t a3, uint32_t b0, uint32_t b1) {
    asm volatile(
        "mma.sync.aligned.m16n8k16.row.col.f32.f16.f16.f32 "
        "{%0,%1,%2,%3},{%4,%5,%6,%7},{%8,%9},{%0,%1,%2,%3};"
        : "+f"(c[0]), "+f"(c[1]), "+f"(c[2]), "+f"(c[3])
        : "r"(a0), "r"(a1), "r"(a2), "r"(a3), "r"(b0), "r"(b1));
}

// ---------------- setup: fp16 conversion, zero states ----------
__global__ void setup_kernel(const float* __restrict__ X,
                             const float* __restrict__ eWih0, const float* __restrict__ eWhh0,
                             const float* __restrict__ eWih1, const float* __restrict__ eWhh1,
                             const float* __restrict__ dWhh0,
                             const float* __restrict__ dWih1, const float* __restrict__ dWhh1)
{
    const size_t s0 = (size_t)G4 * 1088;
    const size_t s1 = (size_t)G4 * 2048;
    const size_t s2 = (size_t)G4 * 2048;
    const size_t s3 = (size_t)G4 * 1024;
    const size_t sx = (size_t)BB * SS * DD;
    const size_t s4 = (size_t)4 * BB * HH;
    const size_t s5 = BB;
    const size_t total = s0 + s1 + s2 + s3 + sx + s4 + s5;

    for (size_t i = (size_t)blockIdx.x * blockDim.x + threadIdx.x; i < total;
         i += (size_t)gridDim.x * blockDim.x) {
        size_t x = i;
        if (x < s0) {
            size_t r = x / 1088, k = x % 1088;
            float v = (k < 1024) ? eWhh0[r * 1024 + k] : eWih0[r * 64 + (k - 1024)];
            g_W0enc[x] = __float2half_rn(v);
            continue;
        }
        x -= s0;
        if (x < s1) {
            size_t r = x / 2048, k = x % 2048;
            float v = (k < 1024) ? eWhh1[r * 1024 + k] : eWih1[r * 1024 + (k - 1024)];
            g_W1enc[x] = __float2half_rn(v);
            continue;
        }
        x -= s1;
        if (x < s2) {
            size_t r = x / 2048, k = x % 2048;
            float v = (k < 1024) ? dWhh1[r * 1024 + k] : dWih1[r * 1024 + (k - 1024)];
            g_W1dec[x] = __float2half_rn(v);
            continue;
        }
        x -= s2;
        if (x < s3) { g_W0dec[x] = __float2half_rn(dWhh0[x]); continue; }
        x -= s3;
        if (x < sx) { g_X[x] = __float2half_rn(X[x]); continue; }
        x -= sx;
        if (x < s4) {
            size_t seg = x / ((size_t)BB * HH);
            size_t off = x % ((size_t)BB * HH);
            if (seg == 0) g_h0[0][off] = __float2half_rn(0.0f);
            else if (seg == 1) g_h1[0][off] = __float2half_rn(0.0f);
            else if (seg == 2) g_c0[off] = 0.0f;
            else g_c1[off] = 0.0f;
            continue;
        }
        x -= s4;
        g_pred[x] = 0.0f;
    }
}

// ---------------- fused LSTM cell GEMM: ldmatrix + mma.m16n8k16 ------------
// CTA: 256 threads = 8 warps (4m x 2n), warp tile 32x32. CTA tile M=128 x N=64.
// K-chunk 64 halfs, 4-stage cp.async ring, 2 CTAs/SM, grid 256 per role-pair.
#define NSTG 4
#define MT 128
#define KC 64
#define ASZ (MT * APAD)              // halfs
#define BSZ (64 * APAD)
#define STG_H (ASZ + BSZ)            // halfs per stage
#define SMEM_BYTES (NSTG * STG_H * 2)   // 110592 B
#define CPAD 72                      // C row stride (floats)

struct Role {
    const __half* W;       // weight, row-major [4096, K]
    const __half* Ah;      // h part of A (row stride HH)
    const __half* aux;     // second A part base
    size_t aux_stride;     // row stride of aux
    __half* hout;
    float* c_io;
    const float* bias;     // [4096]
    const float* sw;       // scalar-input weights [4096] or null
    int K;
};

__device__ __forceinline__ void cell_body(const Role& R, int mt, int jt, __half* smem, int tid)
{
    const int j0 = jt * 16;
    const int m0 = mt * MT;
    const int warp = tid >> 5, lane = tid & 31;
    const int wm = warp & 3;       // m sub-tile (32 rows)
    const int wn = warp >> 2;      // n sub-tile (32 cols)
    const int nch = R.K / KC;
    const uint32_t sb = smem_u32(smem);

    // per-lane ldmatrix byte offsets within a stage (proven mappings from R11)
    const uint32_t aOff =
        ((uint32_t)(wm * 32 + (lane & 15)) * APAD + ((lane >> 4) & 1) * 8) * 2;
    const uint32_t bOff = (uint32_t)ASZ * 2 +
        ((uint32_t)(wn * 32 + ((lane & 16) >> 1) + (lane & 7)) * APAD + ((lane & 8) ? 8 : 0)) * 2;

    auto load_chunk = [&](int ck) {
        __half* a = smem + (ck & (NSTG - 1)) * STG_H;
        __half* b = a + ASZ;
        const int kk = ck * KC;
#pragma unroll
        for (int it = 0; it < 4; it++) {
            int u = tid + it * 256;          // 0..1023 : 128 rows x 8 segs
            int r = u >> 3, c8 = (u & 7) << 3;
            int kg = kk + c8;
            const __half* src = (kg < 1024)
                ? R.Ah + (size_t)(m0 + r) * HH + kg
                : R.aux + (size_t)(m0 + r) * R.aux_stride + (kg - 1024);
            cpa16(a + r * APAD + c8, src);
        }
#pragma unroll
        for (int it = 0; it < 2; it++) {
            int u = tid + it * 256;          // 0..511 : 64 rows x 8 segs
            int n = u >> 3, c8 = (u & 7) << 3;
            int g = n >> 4, jj = n & 15;
            const __half* src = R.W + (size_t)(g * 1024 + j0 + jj) * R.K + kk + c8;
            cpa16(b + n * APAD + c8, src);
        }
        cpa_commit();
    };

    float acc[2][4][4];
#pragma unroll
    for (int mi = 0; mi < 2; mi++)
#pragma unroll
        for (int ni = 0; ni < 4; ni++)
#pragma unroll
            for (int e = 0; e < 4; e++) acc[mi][ni][e] = 0.0f;

    load_chunk(0);
    load_chunk(1);
    load_chunk(2);

    for (int ck = 0; ck < nch; ck++) {
        if (ck == nch - 1)      cpa_wait0();
        else if (ck == nch - 2) cpa_wait1();
        else                    cpa_wait2();
        __syncthreads();

        if (ck + NSTG - 1 < nch) load_chunk(ck + NSTG - 1);

        const uint32_t stg = sb + (uint32_t)(ck & (NSTG - 1)) * (STG_H * 2);
#pragma unroll
        for (int k16 = 0; k16 < KC / 16; k16++) {
            const uint32_t kb = (uint32_t)k16 * 32;   // 16 halfs = 32B
            uint32_t b0[4], b1[4];
            ldsm_x4(b0[0], b0[1], b0[2], b0[3], stg + bOff + kb);                  // n-tiles 0,1
            ldsm_x4(b1[0], b1[1], b1[2], b1[3], stg + bOff + kb + 16 * APAD * 2);  // n-tiles 2,3
#pragma unroll
            for (int mi = 0; mi < 2; mi++) {
                uint32_t a0, a1, a2, a3;
                ldsm_x4(a0, a1, a2, a3, stg + aOff + kb + (uint32_t)mi * 16 * APAD * 2);
                mma16816(acc[mi][0], a0, a1, a2, a3, b0[0], b0[1]);
                mma16816(acc[mi][1], a0, a1, a2, a3, b0[2], b0[3]);
                mma16816(acc[mi][2], a0, a1, a2, a3, b1[0], b1[1]);
                mma16816(acc[mi][3], a0, a1, a2, a3, b1[2], b1[3]);
            }
        }
    }
    __syncthreads();   // compute done before C overwrites stage smem

    // --- epilogue: dump C [128][CPAD] fp32, cell update ---
    float* Cs = (float*)smem;
    {
        const int rr = lane >> 2, cc = 2 * (lane & 3);
#pragma unroll
        for (int mi = 0; mi < 2; mi++)
#pragma unroll
            for (int ni = 0; ni < 4; ni++) {
                int r0 = wm * 32 + mi * 16 + rr;
                int c0 = wn * 32 + ni * 8 + cc;
                Cs[r0 * CPAD + c0]           = acc[mi][ni][0];
                Cs[r0 * CPAD + c0 + 1]       = acc[mi][ni][1];
                Cs[(r0 + 8) * CPAD + c0]     = acc[mi][ni][2];
                Cs[(r0 + 8) * CPAD + c0 + 1] = acc[mi][ni][3];
            }
    }
    __syncthreads();

#pragma unroll
    for (int e = 0; e < 8; e++) {
        int idx = tid + e * 256;     // 0..2047 = 128 rows x 16 j
        int r = idx >> 4;
        int jj = idx & 15;
        int b = m0 + r;
        int j = j0 + jj;

        float gi = Cs[r * CPAD + 0 * 16 + jj] + R.bias[j];
        float gf = Cs[r * CPAD + 1 * 16 + jj] + R.bias[1024 + j];
        float gg = Cs[r * CPAD + 2 * 16 + jj] + R.bias[2048 + j];
        float go = Cs[r * CPAD + 3 * 16 + jj] + R.bias[3072 + j];

        if (R.sw) {
            float p = g_pred[b];
            gi += p * R.sw[j];
            gf += p * R.sw[1024 + j];
            gg += p * R.sw[2048 + j];
            go += p * R.sw[3072 + j];
        }

        size_t o = (size_t)b * HH + j;
        float c  = R.c_io[o];
        float cn = sigmoidf_(gf) * c + sigmoidf_(gi) * tanhf(gg);
        float hn = sigmoidf_(go) * tanhf(cn);
        R.c_io[o] = cn;
        R.hout[o] = __float2half_rn(hn);
    }
}

// mode: 0 = encoder fused [L1(t) | L0(t+1)], 1 = enc L0(t), 2 = enc L1(t),
//       3 = dec L0(t), 4 = dec L1(t)
__global__ void __launch_bounds__(256, 2)
cell_kernel(const float* __restrict__ bias0, const float* __restrict__ bias1,
            const float* __restrict__ sw0, int t, int par, int mode)
{
    extern __shared__ __half smem[];
    const int tid = threadIdx.x;

    int roleL1, local;
    if (mode == 0) { roleL1 = (blockIdx.x < 128); local = blockIdx.x & 127; }
    else           { roleL1 = (mode == 2 || mode == 4); local = blockIdx.x; }
    const int mt = local & 1;
    const int jt = local >> 1;

    Role R;
    if (mode <= 2) {
        if (roleL1) {  // encoder layer 1, step t
            R.W = g_W1enc; R.K = 2048;
            R.Ah = g_h1[par]; R.aux = g_h0[par ^ 1]; R.aux_stride = HH;
            R.hout = g_h1[par ^ 1]; R.c_io = g_c1;
            R.bias = bias1; R.sw = nullptr;
        } else {       // encoder layer 0, step s
            int s, parS;
            if (mode == 0) { s = t + 1; parS = par ^ 1; }
            else           { s = t;     parS = par;     }
            R.W = g_W0enc; R.K = 1088;
            R.Ah = g_h0[parS]; R.aux = g_X + (size_t)s * DD; R.aux_stride = (size_t)SS * DD;
            R.hout = g_h0[parS ^ 1]; R.c_io = g_c0;
            R.bias = bias0; R.sw = nullptr;
        }
    } else if (mode == 3) {   // decoder layer 0
        R.W = g_W0dec; R.K = 1024;
        R.Ah = g_h0[par]; R.aux = g_h0[par]; R.aux_stride = HH;  // aux unused
        R.hout = g_h0[par ^ 1]; R.c_io = g_c0;
        R.bias = bias0; R.sw = sw0;
    } else {                  // decoder layer 1
        R.W = g_W1dec; R.K = 2048;
        R.Ah = g_h1[par]; R.aux = g_h0[par ^ 1]; R.aux_stride = HH;
        R.hout = g_h1[par ^ 1]; R.c_io = g_c1;
        R.bias = bias1; R.sw = nullptr;
    }

    cell_body(R, mt, jt, smem, tid);
}

// ---------------- fc: pred[b] = dot(h1[b], fcW) + fcb ----------------------
__global__ void fc_kernel(const float* __restrict__ fcW, const float* __restrict__ fcb,
                          float* __restrict__ out, int par, int t)
{
    int gw = (blockIdx.x * blockDim.x + threadIdx.x) >> 5;
    int lane = threadIdx.x & 31;
    if (gw >= BB) return;
    const __half* hr = g_h1[par] + (size_t)gw * HH;
    float s = 0.0f;
#pragma unroll 8
    for (int k = lane; k < HH; k += 32) s += __half2float(hr[k]) * fcW[k];
#pragma unroll
    for (int o = 16; o; o >>= 1) s += __shfl_xor_sync(0xFFFFFFFFu, s, o);
    if (lane == 0) {
        float p = s + fcb[0];
        out[(size_t)gw * TOUT + t] = p;
        g_pred[gw] = p;
    }
}

// ---------------- launch ----------------------------------------------------
extern "C" void kernel_launch(void* const* d_in, const int* in_sizes, int n_in,
                              void* d_out, int out_size)
{
    const float* X     = (const float*)d_in[0];
    const float* eWih0 = (const float*)d_in[1];
    const float* eWhh0 = (const float*)d_in[2];
    const float* eb0   = (const float*)d_in[3];
    const float* eWih1 = (const float*)d_in[4];
    const float* eWhh1 = (const float*)d_in[5];
    const float* eb1   = (const float*)d_in[6];
    const float* dWih0 = (const float*)d_in[7];
    const float* dWhh0 = (const float*)d_in[8];
    const float* db0   = (const float*)d_in[9];
    const float* dWih1 = (const float*)d_in[10];
    const float* dWhh1 = (const float*)d_in[11];
    const float* db1   = (const float*)d_in[12];
    const float* fcW   = (const float*)d_in[13];
    const float* fcb   = (const float*)d_in[14];
    float* out         = (float*)d_out;

    cudaFuncSetAttribute(cell_kernel, cudaFuncAttributeMaxDynamicSharedMemorySize,
                         SMEM_BYTES);

    setup_kernel<<<1024, 256>>>(X, eWih0, eWhh0, eWih1, eWhh1, dWhh0, dWih1, dWhh1);

    // encoder: software-pipelined wavefront (L1(t) runs with L0(t+1) in one launch)
    cell_kernel<<<128, 256, SMEM_BYTES>>>(eb0, nullptr, nullptr, 0, 0, 1);      // L0(0)
    for (int t = 0; t < SS - 1; t++)
        cell_kernel<<<256, 256, SMEM_BYTES>>>(eb0, eb1, nullptr, t, t & 1, 0);  // L1(t)+L0(t+1)
    cell_kernel<<<128, 256, SMEM_BYTES>>>(nullptr, eb1, nullptr, SS - 1, (SS - 1) & 1, 2);

    // decoder (final enc states in g_h0[0], g_h1[0])
    int par = 0;
    for (int t = 0; t < TOUT; t++) {
        cell_kernel<<<128, 256, SMEM_BYTES>>>(db0, nullptr, dWih0, t, par, 3);
        cell_kernel<<<128, 256, SMEM_BYTES>>>(nullptr, db1, nullptr, t, par, 4);
        fc_kernel<<<8, 1024>>>(fcW, fcb, out, par ^ 1, t);
        par ^= 1;
    }
}

// round 13
// speedup vs baseline: 1.3609x; 1.0513x over previous
#include <cuda_runtime.h>
#include <cuda_fp16.h>
#include <cstdint>

#define BB 256      // batch
#define SS 256      // encoder seq len
#define DD 64       // input dim
#define HH 1024     // hidden
#define G4 4096     // 4*H
#define TOUT 32     // decode steps
#define XP 128      // padded X row (halfs)
#define K0P 1152    // padded K for enc L0 (1024 h + 64 X + 64 zero)
#define KPAD 136    // smem row stride (halfs) = 272B

// ---------------- static device scratch (fp16 operands, fp32 state) --------
__device__ __half g_W0enc[(size_t)G4 * K0P];    // [Whh0 | Wih0 | 0] rows padded
__device__ __half g_W1enc[(size_t)G4 * 2048];   // [Whh1 | Wih1]
__device__ __half g_W0dec[(size_t)G4 * 1024];   // dec Whh0
__device__ __half g_W1dec[(size_t)G4 * 2048];   // [dec Whh1 | dec Wih1]
__device__ __half g_Xp[(size_t)BB * SS * XP];   // X padded to 128 cols (64 zeros)
__device__ __half g_h0[2][BB * HH];
__device__ __half g_h1[2][BB * HH];
__device__ float  g_c0[BB * HH];
__device__ float  g_c1[BB * HH];
__device__ float  g_pred[BB];

__device__ __forceinline__ float sigmoidf_(float x) { return 1.0f / (1.0f + expf(-x)); }

__device__ __forceinline__ void cpa16(void* s, const void* g) {
    unsigned sa = (unsigned)__cvta_generic_to_shared(s);
    asm volatile("cp.async.ca.shared.global [%0], [%1], 16;\n" ::"r"(sa), "l"(g));
}
__device__ __forceinline__ void cpa_commit() { asm volatile("cp.async.commit_group;\n"); }
__device__ __forceinline__ void cpa_wait0() { asm volatile("cp.async.wait_group 0;\n"); }

__device__ __forceinline__ uint32_t smem_u32(const void* p) {
    uint32_t a;
    asm("{ .reg .u64 t; cvta.to.shared.u64 t, %1; cvt.u32.u64 %0, t; }" : "=r"(a) : "l"(p));
    return a;
}
__device__ __forceinline__ void ldsm_x4(uint32_t& r0, uint32_t& r1, uint32_t& r2, uint32_t& r3,
                                        uint32_t addr) {
    asm volatile("ldmatrix.sync.aligned.m8n8.x4.shared.b16 {%0,%1,%2,%3}, [%4];"
                 : "=r"(r0), "=r"(r1), "=r"(r2), "=r"(r3) : "r"(addr));
}
__device__ __forceinline__ void mma16816(float* c, uint32_t a0, uint32_t a1, uint32_t a2,
                                         uint32_t a3, uint32_t b0, uint32_t b1) {
    asm volatile(
        "mma.sync.aligned.m16n8k16.row.col.f32.f16.f16.f32 "
        "{%0,%1,%2,%3},{%4,%5,%6,%7},{%8,%9},{%0,%1,%2,%3};"
        : "+f"(c[0]), "+f"(c[1]), "+f"(c[2]), "+f"(c[3])
        : "r"(a0), "r"(a1), "r"(a2), "r"(a3), "r"(b0), "r"(b1));
}

// ---------------- setup: fp16 conversion + padding, zero states ----------
__global__ void setup_kernel(const float* __restrict__ X,
                             const float* __restrict__ eWih0, const float* __restrict__ eWhh0,
                             const float* __restrict__ eWih1, const float* __restrict__ eWhh1,
                             const float* __restrict__ dWhh0,
                             const float* __restrict__ dWih1, const float* __restrict__ dWhh1)
{
    const size_t s0 = (size_t)G4 * K0P;
    const size_t s1 = (size_t)G4 * 2048;
    const size_t s2 = (size_t)G4 * 2048;
    const size_t s3 = (size_t)G4 * 1024;
    const size_t sx = (size_t)BB * SS * XP;
    const size_t s4 = (size_t)4 * BB * HH;
    const size_t s5 = BB;
    const size_t total = s0 + s1 + s2 + s3 + sx + s4 + s5;

    for (size_t i = (size_t)blockIdx.x * blockDim.x + threadIdx.x; i < total;
         i += (size_t)gridDim.x * blockDim.x) {
        size_t x = i;
        if (x < s0) {   // W0enc rows padded to 1152
            size_t r = x / K0P, k = x % K0P;
            float v = (k < 1024) ? eWhh0[r * 1024 + k]
                    : (k < 1088) ? eWih0[r * 64 + (k - 1024)] : 0.0f;
            g_W0enc[x] = __float2half_rn(v);
            continue;
        }
        x -= s0;
        if (x < s1) {
            size_t r = x / 2048, k = x % 2048;
            float v = (k < 1024) ? eWhh1[r * 1024 + k] : eWih1[r * 1024 + (k - 1024)];
            g_W1enc[x] = __float2half_rn(v);
            continue;
        }
        x -= s1;
        if (x < s2) {
            size_t r = x / 2048, k = x % 2048;
            float v = (k < 1024) ? dWhh1[r * 1024 + k] : dWih1[r * 1024 + (k - 1024)];
            g_W1dec[x] = __float2half_rn(v);
            continue;
        }
        x -= s2;
        if (x < s3) { g_W0dec[x] = __float2half_rn(dWhh0[x]); continue; }
        x -= s3;
        if (x < sx) {   // X padded: [b][s][128], cols 64..127 zero
            size_t bs = x / XP, c = x % XP;
            g_Xp[x] = __float2half_rn(c < DD ? X[bs * DD + c] : 0.0f);
            continue;
        }
        x -= sx;
        if (x < s4) {
            size_t seg = x / ((size_t)BB * HH);
            size_t off = x % ((size_t)BB * HH);
            if (seg == 0) g_h0[0][off] = __float2half_rn(0.0f);
            else if (seg == 1) g_h1[0][off] = __float2half_rn(0.0f);
            else if (seg == 2) g_c0[off] = 0.0f;
            else g_c1[off] = 0.0f;
            continue;
        }
        x -= s4;
        g_pred[x] = 0.0f;
    }
}

// ---------------- fused LSTM cell GEMM: ldmatrix + mma, KC=128 -------------
// CTA: 256 threads = 8 warps (4m x 2n), warp tile 32x32. CTA tile M=128 x N=64.
// K-chunk 128 halfs, 2-stage cp.async ring, 2 CTAs/SM.
// Warps stagger their k16 order ((warp+i)&7) to overlap LDSM and MMA phases.
#define NSTG 2
#define MT 128
#define KC 128
#define ASZ (MT * KPAD)              // halfs
#define BSZ (64 * KPAD)
#define STG_H (ASZ + BSZ)            // halfs per stage
#define SMEM_BYTES (NSTG * STG_H * 2)   // 104448 B
#define CPAD 72                      // C row stride (floats)

struct Role {
    const __half* W;       // weight, row-major [4096, K]
    const __half* Ah;      // h part of A (row stride HH)
    const __half* aux;     // second A part base (row stride aux_stride)
    size_t aux_stride;
    __half* hout;
    float* c_io;
    const float* bias;     // [4096]
    const float* sw;       // scalar-input weights [4096] or null
    int K;                 // padded K, divisible by 128
};

__device__ __forceinline__ void cell_body(const Role& R, int mt, int jt, __half* smem, int tid)
{
    const int j0 = jt * 16;
    const int m0 = mt * MT;
    const int warp = tid >> 5, lane = tid & 31;
    const int wm = warp & 3;       // m sub-tile (32 rows)
    const int wn = warp >> 2;      // n sub-tile (32 cols)
    const int nch = R.K / KC;
    const uint32_t sb = smem_u32(smem);

    // per-lane ldmatrix byte offsets within a stage
    const uint32_t aOff =
        ((uint32_t)(wm * 32 + (lane & 15)) * KPAD + ((lane >> 4) & 1) * 8) * 2;
    const uint32_t bOff = (uint32_t)ASZ * 2 +
        ((uint32_t)(wn * 32 + ((lane & 16) >> 1) + (lane & 7)) * KPAD + ((lane & 8) ? 8 : 0)) * 2;

    auto load_chunk = [&](int ck) {
        __half* a = smem + (ck & (NSTG - 1)) * STG_H;
        __half* b = a + ASZ;
        const int kk = ck * KC;
#pragma unroll
        for (int it = 0; it < 8; it++) {
            int u = tid + it * 256;          // 0..2047 : 128 rows x 16 segs
            int r = u >> 4, c8 = (u & 15) << 3;
            int kg = kk + c8;
            const __half* src = (kg < 1024)
                ? R.Ah + (size_t)(m0 + r) * HH + kg
                : R.aux + (size_t)(m0 + r) * R.aux_stride + (kg - 1024);
            cpa16(a + r * KPAD + c8, src);
        }
#pragma unroll
        for (int it = 0; it < 4; it++) {
            int u = tid + it * 256;          // 0..1023 : 64 rows x 16 segs
            int n = u >> 4, c8 = (u & 15) << 3;
            int g = n >> 4, jj = n & 15;
            const __half* src = R.W + (size_t)(g * 1024 + j0 + jj) * R.K + kk + c8;
            cpa16(b + n * KPAD + c8, src);
        }
        cpa_commit();
    };

    float acc[2][4][4];
#pragma unroll
    for (int mi = 0; mi < 2; mi++)
#pragma unroll
        for (int ni = 0; ni < 4; ni++)
#pragma unroll
            for (int e = 0; e < 4; e++) acc[mi][ni][e] = 0.0f;

    load_chunk(0);

    for (int ck = 0; ck < nch; ck++) {
        cpa_wait0();                 // chunk ck landed (2-stage)
        __syncthreads();
        if (ck + 1 < nch) load_chunk(ck + 1);

        const uint32_t stg = sb + (uint32_t)(ck & (NSTG - 1)) * (STG_H * 2);
#pragma unroll
        for (int i = 0; i < KC / 16; i++) {
            const int k16 = (warp + i) & 7;          // staggered schedule
            const uint32_t kb = (uint32_t)k16 * 32;  // 16 halfs = 32B
            uint32_t b0[4], b1[4];
            ldsm_x4(b0[0], b0[1], b0[2], b0[3], stg + bOff + kb);                  // n-tiles 0,1
            ldsm_x4(b1[0], b1[1], b1[2], b1[3], stg + bOff + kb + 16 * KPAD * 2);  // n-tiles 2,3
#pragma unroll
            for (int mi = 0; mi < 2; mi++) {
                uint32_t a0, a1, a2, a3;
                ldsm_x4(a0, a1, a2, a3, stg + aOff + kb + (uint32_t)mi * 16 * KPAD * 2);
                mma16816(acc[mi][0], a0, a1, a2, a3, b0[0], b0[1]);
                mma16816(acc[mi][1], a0, a1, a2, a3, b0[2], b0[3]);
                mma16816(acc[mi][2], a0, a1, a2, a3, b1[0], b1[1]);
                mma16816(acc[mi][3], a0, a1, a2, a3, b1[2], b1[3]);
            }
        }
    }
    __syncthreads();   // compute done before C overwrites stage smem

    // --- epilogue: dump C [128][CPAD] fp32, cell update ---
    float* Cs = (float*)smem;
    {
        const int rr = lane >> 2, cc = 2 * (lane & 3);
#pragma unroll
        for (int mi = 0; mi < 2; mi++)
#pragma unroll
            for (int ni = 0; ni < 4; ni++) {
                int r0 = wm * 32 + mi * 16 + rr;
                int c0 = wn * 32 + ni * 8 + cc;
                Cs[r0 * CPAD + c0]           = acc[mi][ni][0];
                Cs[r0 * CPAD + c0 + 1]       = acc[mi][ni][1];
                Cs[(r0 + 8) * CPAD + c0]     = acc[mi][ni][2];
                Cs[(r0 + 8) * CPAD + c0 + 1] = acc[mi][ni][3];
            }
    }
    __syncthreads();

#pragma unroll
    for (int e = 0; e < 8; e++) {
        int idx = tid + e * 256;     // 0..2047 = 128 rows x 16 j
        int r = idx >> 4;
        int jj = idx & 15;
        int b = m0 + r;
        int j = j0 + jj;

        float gi = Cs[r * CPAD + 0 * 16 + jj] + R.bias[j];
        float gf = Cs[r * CPAD + 1 * 16 + jj] + R.bias[1024 + j];
        float gg = Cs[r * CPAD + 2 * 16 + jj] + R.bias[2048 + j];
        float go = Cs[r * CPAD + 3 * 16 + jj] + R.bias[3072 + j];

        if (R.sw) {
            float p = g_pred[b];
            gi += p * R.sw[j];
            gf += p * R.sw[1024 + j];
            gg += p * R.sw[2048 + j];
            go += p * R.sw[3072 + j];
        }

        size_t o = (size_t)b * HH + j;
        float c  = R.c_io[o];
        float cn = sigmoidf_(gf) * c + sigmoidf_(gi) * tanhf(gg);
        float hn = sigmoidf_(go) * tanhf(cn);
        R.c_io[o] = cn;
        R.hout[o] = __float2half_rn(hn);
    }
}

// mode: 0 = encoder fused [L1(t) | L0(t+1)], 1 = enc L0(t), 2 = enc L1(t),
//       3 = dec L0(t), 4 = dec L1(t)
__global__ void __launch_bounds__(256, 2)
cell_kernel(const float* __restrict__ bias0, const float* __restrict__ bias1,
            const float* __restrict__ sw0, int t, int par, int mode)
{
    extern __shared__ __half smem[];
    const int tid = threadIdx.x;

    int roleL1, local;
    if (mode == 0) { roleL1 = (blockIdx.x < 128); local = blockIdx.x & 127; }
    else           { roleL1 = (mode == 2 || mode == 4); local = blockIdx.x; }
    const int mt = local & 1;
    const int jt = local >> 1;

    Role R;
    if (mode <= 2) {
        if (roleL1) {  // encoder layer 1, step t
            R.W = g_W1enc; R.K = 2048;
            R.Ah = g_h1[par]; R.aux = g_h0[par ^ 1]; R.aux_stride = HH;
            R.hout = g_h1[par ^ 1]; R.c_io = g_c1;
            R.bias = bias1; R.sw = nullptr;
        } else {       // encoder layer 0, step s (A = [h | Xpad])
            int s, parS;
            if (mode == 0) { s = t + 1; parS = par ^ 1; }
            else           { s = t;     parS = par;     }
            R.W = g_W0enc; R.K = K0P;
            R.Ah = g_h0[parS]; R.aux = g_Xp + (size_t)s * XP; R.aux_stride = (size_t)SS * XP;
            R.hout = g_h0[parS ^ 1]; R.c_io = g_c0;
            R.bias = bias0; R.sw = nullptr;
        }
    } else if (mode == 3) {   // decoder layer 0
        R.W = g_W0dec; R.K = 1024;
        R.Ah = g_h0[par]; R.aux = g_h0[par]; R.aux_stride = HH;  // aux unused (K=1024)
        R.hout = g_h0[par ^ 1]; R.c_io = g_c0;
        R.bias = bias0; R.sw = sw0;
    } else {                  // decoder layer 1
        R.W = g_W1dec; R.K = 2048;
        R.Ah = g_h1[par]; R.aux = g_h0[par ^ 1]; R.aux_stride = HH;
        R.hout = g_h1[par ^ 1]; R.c_io = g_c1;
        R.bias = bias1; R.sw = nullptr;
    }

    cell_body(R, mt, jt, smem, tid);
}

// ---------------- fc: pred[b] = dot(h1[b], fcW) + fcb ----------------------
__global__ void fc_kernel(const float* __restrict__ fcW, const float* __restrict__ fcb,
                          float* __restrict__ out, int par, int t)
{
    int gw = (blockIdx.x * blockDim.x + threadIdx.x) >> 5;
    int lane = threadIdx.x & 31;
    if (gw >= BB) return;
    const __half* hr = g_h1[par] + (size_t)gw * HH;
    float s = 0.0f;
#pragma unroll 8
    for (int k = lane; k < HH; k += 32) s += __half2float(hr[k]) * fcW[k];
#pragma unroll
    for (int o = 16; o; o >>= 1) s += __shfl_xor_sync(0xFFFFFFFFu, s, o);
    if (lane == 0) {
        float p = s + fcb[0];
        out[(size_t)gw * TOUT + t] = p;
        g_pred[gw] = p;
    }
}

// ---------------- launch ----------------------------------------------------
extern "C" void kernel_launch(void* const* d_in, const int* in_sizes, int n_in,
                              void* d_out, int out_size)
{
    const float* X     = (const float*)d_in[0];
    const float* eWih0 = (const float*)d_in[1];
    const float* eWhh0 = (const float*)d_in[2];
    const float* eb0   = (const float*)d_in[3];
    const float* eWih1 = (const float*)d_in[4];
    const float* eWhh1 = (const float*)d_in[5];
    const float* eb1   = (const float*)d_in[6];
    const float* dWih0 = (const float*)d_in[7];
    const float* dWhh0 = (const float*)d_in[8];
    const float* db0   = (const float*)d_in[9];
    const float* dWih1 = (const float*)d_in[10];
    const float* dWhh1 = (const float*)d_in[11];
    const float* db1   = (const float*)d_in[12];
    const float* fcW   = (const float*)d_in[13];
    const float* fcb   = (const float*)d_in[14];
    float* out         = (float*)d_out;

    cudaFuncSetAttribute(cell_kernel, cudaFuncAttributeMaxDynamicSharedMemorySize,
                         SMEM_BYTES);

    setup_kernel<<<1024, 256>>>(X, eWih0, eWhh0, eWih1, eWhh1, dWhh0, dWih1, dWhh1);

    // encoder: software-pipelined wavefront (L1(t) runs with L0(t+1) in one launch)
    cell_kernel<<<128, 256, SMEM_BYTES>>>(eb0, nullptr, nullptr, 0, 0, 1);      // L0(0)
    for (int t = 0; t < SS - 1; t++)
        cell_kernel<<<256, 256, SMEM_BYTES>>>(eb0, eb1, nullptr, t, t & 1, 0);  // L1(t)+L0(t+1)
    cell_kernel<<<128, 256, SMEM_BYTES>>>(nullptr, eb1, nullptr, SS - 1, (SS - 1) & 1, 2);

    // decoder (final enc states in g_h0[0], g_h1[0])
    int par = 0;
    for (int t = 0; t < TOUT; t++) {
        cell_kernel<<<128, 256, SMEM_BYTES>>>(db0, nullptr, dWih0, t, par, 3);
        cell_kernel<<<128, 256, SMEM_BYTES>>>(nullptr, db1, nullptr, t, par, 4);
        fc_kernel<<<8, 1024>>>(fcW, fcb, out, par ^ 1, t);
        par ^= 1;
    }
}